// round 2
// baseline (speedup 1.0000x reference)
#include <cuda_runtime.h>
#include <cuda_bf16.h>
#include <math_constants.h>

// Problem constants
#define B_ 8
#define S_ 1024
#define H_ 1024
#define NH_ 16
#define HD_ 64
#define M_ (B_ * S_)        // 8192
#define LN_EPS 1e-12f

// Scratch (allocation-free rule: __device__ globals)
__device__ float g_Q[M_ * H_];    // [B*NH][S][HD]
__device__ float g_K[M_ * H_];
__device__ float g_V[M_ * H_];
__device__ float g_ctx[M_ * H_];  // [B,S,H]
__device__ float g_x[M_ * H_];    // residual-added pre-LN

// ---------------------------------------------------------------------------
// Tiled SGEMM: C[m][n] = sum_k A[m][k] * W[n][k]  (both K-major, torch Linear)
// BM=BN=128, BK=16, 256 threads, 8x8 per thread.
// ---------------------------------------------------------------------------

// QKV fused: grid (N/128=8, M/128=64, 3)
__global__ __launch_bounds__(256) void qkv_gemm_kernel(
    const float* __restrict__ X,
    const float* __restrict__ Wq, const float* __restrict__ bq,
    const float* __restrict__ Wk, const float* __restrict__ bk,
    const float* __restrict__ Wv, const float* __restrict__ bv)
{
    const float* W; const float* bias; float* out;
    if (blockIdx.z == 0)      { W = Wq; bias = bq; out = g_Q; }
    else if (blockIdx.z == 1) { W = Wk; bias = bk; out = g_K; }
    else                      { W = Wv; bias = bv; out = g_V; }

    __shared__ float As[16][128];
    __shared__ float Bs[16][128];

    const int tid = threadIdx.x;
    const int n0 = blockIdx.x * 128;
    const int m0 = blockIdx.y * 128;
    const int tx = tid & 15;        // 0..15 -> 8 cols each
    const int ty = tid >> 4;        // 0..15 -> 8 rows each
    const int lr = tid >> 2;        // 0..63 load row
    const int lc = (tid & 3) * 4;   // 0,4,8,12 load col

    float acc[8][8];
    #pragma unroll
    for (int i = 0; i < 8; i++)
        #pragma unroll
        for (int j = 0; j < 8; j++) acc[i][j] = 0.f;

    for (int k0 = 0; k0 < H_; k0 += 16) {
        #pragma unroll
        for (int rr = 0; rr < 2; rr++) {
            int r = lr + rr * 64;
            float4 a = *(const float4*)&X[(size_t)(m0 + r) * H_ + k0 + lc];
            As[lc + 0][r] = a.x; As[lc + 1][r] = a.y;
            As[lc + 2][r] = a.z; As[lc + 3][r] = a.w;
            float4 b = *(const float4*)&W[(size_t)(n0 + r) * H_ + k0 + lc];
            Bs[lc + 0][r] = b.x; Bs[lc + 1][r] = b.y;
            Bs[lc + 2][r] = b.z; Bs[lc + 3][r] = b.w;
        }
        __syncthreads();

        #pragma unroll
        for (int k = 0; k < 16; k++) {
            float a[8], b[8];
            *(float4*)&a[0] = *(const float4*)&As[k][ty * 8];
            *(float4*)&a[4] = *(const float4*)&As[k][ty * 8 + 4];
            *(float4*)&b[0] = *(const float4*)&Bs[k][tx * 8];
            *(float4*)&b[4] = *(const float4*)&Bs[k][tx * 8 + 4];
            #pragma unroll
            for (int i = 0; i < 8; i++)
                #pragma unroll
                for (int j = 0; j < 8; j++)
                    acc[i][j] = fmaf(a[i], b[j], acc[i][j]);
        }
        __syncthreads();
    }

    float bj[8];
    #pragma unroll
    for (int j = 0; j < 8; j++) bj[j] = bias[n0 + tx * 8 + j];

    #pragma unroll
    for (int i = 0; i < 8; i++) {
        int m = m0 + ty * 8 + i;
        int bb = m >> 10;           // batch
        int ss = m & 1023;          // seq
        #pragma unroll
        for (int j = 0; j < 8; j++) {
            int n = n0 + tx * 8 + j;
            int h = n >> 6, d = n & 63;
            out[((size_t)(bb * NH_ + h) * S_ + ss) * HD_ + d] = acc[i][j] + bj[j];
        }
    }
}

// Output projection + bias + residual: grid (8, 64)
__global__ __launch_bounds__(256) void out_gemm_kernel(
    const float* __restrict__ Wo, const float* __restrict__ bo,
    const float* __restrict__ residual)
{
    __shared__ float As[16][128];
    __shared__ float Bs[16][128];

    const float* A = g_ctx;
    const int tid = threadIdx.x;
    const int n0 = blockIdx.x * 128;
    const int m0 = blockIdx.y * 128;
    const int tx = tid & 15;
    const int ty = tid >> 4;
    const int lr = tid >> 2;
    const int lc = (tid & 3) * 4;

    float acc[8][8];
    #pragma unroll
    for (int i = 0; i < 8; i++)
        #pragma unroll
        for (int j = 0; j < 8; j++) acc[i][j] = 0.f;

    for (int k0 = 0; k0 < H_; k0 += 16) {
        #pragma unroll
        for (int rr = 0; rr < 2; rr++) {
            int r = lr + rr * 64;
            float4 a = *(const float4*)&A[(size_t)(m0 + r) * H_ + k0 + lc];
            As[lc + 0][r] = a.x; As[lc + 1][r] = a.y;
            As[lc + 2][r] = a.z; As[lc + 3][r] = a.w;
            float4 b = *(const float4*)&Wo[(size_t)(n0 + r) * H_ + k0 + lc];
            Bs[lc + 0][r] = b.x; Bs[lc + 1][r] = b.y;
            Bs[lc + 2][r] = b.z; Bs[lc + 3][r] = b.w;
        }
        __syncthreads();

        #pragma unroll
        for (int k = 0; k < 16; k++) {
            float a[8], b[8];
            *(float4*)&a[0] = *(const float4*)&As[k][ty * 8];
            *(float4*)&a[4] = *(const float4*)&As[k][ty * 8 + 4];
            *(float4*)&b[0] = *(const float4*)&Bs[k][tx * 8];
            *(float4*)&b[4] = *(const float4*)&Bs[k][tx * 8 + 4];
            #pragma unroll
            for (int i = 0; i < 8; i++)
                #pragma unroll
                for (int j = 0; j < 8; j++)
                    acc[i][j] = fmaf(a[i], b[j], acc[i][j]);
        }
        __syncthreads();
    }

    float bj[8];
    #pragma unroll
    for (int j = 0; j < 8; j++) bj[j] = bo[n0 + tx * 8 + j];

    #pragma unroll
    for (int i = 0; i < 8; i++) {
        int m = m0 + ty * 8 + i;
        #pragma unroll
        for (int j = 0; j < 8; j++) {
            int n = n0 + tx * 8 + j;
            size_t idx = (size_t)m * H_ + n;
            g_x[idx] = acc[i][j] + bj[j] + residual[idx];
        }
    }
}

// ---------------------------------------------------------------------------
// Flash attention: 1 thread = 1 query row. grid (S/128=8, B*NH=128), 128 thr.
// K/V streamed through smem in 32x64 tiles. Online softmax.
// ---------------------------------------------------------------------------
__global__ __launch_bounds__(128) void attn_kernel(const float* __restrict__ mask)
{
    const int bh  = blockIdx.y;            // b*16 + h
    const int qt  = blockIdx.x;
    const int tid = threadIdx.x;
    const int b   = bh >> 4;
    const int h   = bh & 15;

    const float* Qp = g_Q + (size_t)bh * S_ * HD_;
    const float* Kp = g_K + (size_t)bh * S_ * HD_;
    const float* Vp = g_V + (size_t)bh * S_ * HD_;

    const int sq = qt * 128 + tid;         // query position

    float4 q[16];
    #pragma unroll
    for (int i = 0; i < 16; i++) q[i] = *(const float4*)&Qp[(size_t)sq * HD_ + i * 4];

    float4 acc[16];
    #pragma unroll
    for (int i = 0; i < 16; i++) acc[i] = make_float4(0.f, 0.f, 0.f, 0.f);

    float mx = -CUDART_INF_F;
    float l  = 0.f;

    __shared__ float Ks[32][64];
    __shared__ float Vs[32][64];

    for (int kt = 0; kt < S_ / 32; kt++) {
        // cooperative load: 2048 floats each = 4 float4 per thread
        #pragma unroll
        for (int it = 0; it < 4; it++) {
            int f = it * 128 + tid;        // 0..511 float4 index
            int j = f >> 4;                // row 0..31
            int c = (f & 15) * 4;          // col
            *(float4*)&Ks[j][c] = *(const float4*)&Kp[(size_t)(kt * 32 + j) * HD_ + c];
            *(float4*)&Vs[j][c] = *(const float4*)&Vp[(size_t)(kt * 32 + j) * HD_ + c];
        }
        __syncthreads();

        float s[32];
        #pragma unroll
        for (int j = 0; j < 32; j++) {
            const float4* kr = (const float4*)Ks[j];
            float sv = 0.f;
            #pragma unroll
            for (int i = 0; i < 16; i++) {
                float4 kk = kr[i];
                sv = fmaf(q[i].x, kk.x, sv);
                sv = fmaf(q[i].y, kk.y, sv);
                sv = fmaf(q[i].z, kk.z, sv);
                sv = fmaf(q[i].w, kk.w, sv);
            }
            s[j] = sv * 0.125f + mask[b * S_ + kt * 32 + j];
        }

        float tmax = mx;
        #pragma unroll
        for (int j = 0; j < 32; j++) tmax = fmaxf(tmax, s[j]);

        float scale = __expf(mx - tmax);
        mx = tmax;
        l *= scale;
        #pragma unroll
        for (int i = 0; i < 16; i++) {
            acc[i].x *= scale; acc[i].y *= scale;
            acc[i].z *= scale; acc[i].w *= scale;
        }

        #pragma unroll
        for (int j = 0; j < 32; j++) {
            float p = __expf(s[j] - mx);
            l += p;
            const float4* vr = (const float4*)Vs[j];
            #pragma unroll
            for (int i = 0; i < 16; i++) {
                float4 vv = vr[i];
                acc[i].x = fmaf(p, vv.x, acc[i].x);
                acc[i].y = fmaf(p, vv.y, acc[i].y);
                acc[i].z = fmaf(p, vv.z, acc[i].z);
                acc[i].w = fmaf(p, vv.w, acc[i].w);
            }
        }
        __syncthreads();
    }

    float inv = 1.f / l;
    float* op = g_ctx + ((size_t)(b * S_ + sq)) * H_ + h * HD_;
    #pragma unroll
    for (int i = 0; i < 16; i++) {
        float4 o;
        o.x = acc[i].x * inv; o.y = acc[i].y * inv;
        o.z = acc[i].z * inv; o.w = acc[i].w * inv;
        *(float4*)&op[i * 4] = o;
    }
}

// ---------------------------------------------------------------------------
// LayerNorm: one 256-thread block per row (1024 elems, 4 per thread)
// ---------------------------------------------------------------------------
__global__ __launch_bounds__(256) void ln_kernel(
    const float* __restrict__ gamma, const float* __restrict__ beta,
    float* __restrict__ out)
{
    const int row = blockIdx.x;
    const int tid = threadIdx.x;
    const float* x = g_x + (size_t)row * H_;

    float4 v = *(const float4*)&x[tid * 4];
    float s  = v.x + v.y + v.z + v.w;
    float ss = v.x * v.x + v.y * v.y + v.z * v.z + v.w * v.w;

    // warp reduce
    #pragma unroll
    for (int o = 16; o > 0; o >>= 1) {
        s  += __shfl_xor_sync(0xffffffffu, s,  o);
        ss += __shfl_xor_sync(0xffffffffu, ss, o);
    }
    __shared__ float rs[8], rss[8];
    int wid = tid >> 5, lid = tid & 31;
    if (lid == 0) { rs[wid] = s; rss[wid] = ss; }
    __syncthreads();
    if (wid == 0) {
        float a = (lid < 8) ? rs[lid]  : 0.f;
        float c = (lid < 8) ? rss[lid] : 0.f;
        #pragma unroll
        for (int o = 4; o > 0; o >>= 1) {
            a += __shfl_xor_sync(0xffffffffu, a, o);
            c += __shfl_xor_sync(0xffffffffu, c, o);
        }
        if (lid == 0) { rs[0] = a; rss[0] = c; }
    }
    __syncthreads();

    float mean = rs[0] * (1.f / H_);
    float var  = rss[0] * (1.f / H_) - mean * mean;
    float rstd = rsqrtf(var + LN_EPS);

    float4 g = *(const float4*)&gamma[tid * 4];
    float4 bt = *(const float4*)&beta[tid * 4];
    float4 y;
    y.x = (v.x - mean) * rstd * g.x + bt.x;
    y.y = (v.y - mean) * rstd * g.y + bt.y;
    y.z = (v.z - mean) * rstd * g.z + bt.z;
    y.w = (v.w - mean) * rstd * g.w + bt.w;
    *(float4*)&out[(size_t)row * H_ + tid * 4] = y;
}

// ---------------------------------------------------------------------------
extern "C" void kernel_launch(void* const* d_in, const int* in_sizes, int n_in,
                              void* d_out, int out_size)
{
    const float* hidden = (const float*)d_in[0];
    const float* mask   = (const float*)d_in[1];
    const float* Wq     = (const float*)d_in[2];
    const float* bq     = (const float*)d_in[3];
    const float* Wk     = (const float*)d_in[4];
    const float* bk     = (const float*)d_in[5];
    const float* Wv     = (const float*)d_in[6];
    const float* bv     = (const float*)d_in[7];
    const float* Wo     = (const float*)d_in[8];
    const float* bo     = (const float*)d_in[9];
    const float* gamma  = (const float*)d_in[10];
    const float* beta   = (const float*)d_in[11];
    float* out          = (float*)d_out;

    dim3 qkv_grid(H_ / 128, M_ / 128, 3);
    qkv_gemm_kernel<<<qkv_grid, 256>>>(hidden, Wq, bq, Wk, bk, Wv, bv);

    dim3 attn_grid(S_ / 128, B_ * NH_);
    attn_kernel<<<attn_grid, 128>>>(mask);

    dim3 out_grid(H_ / 128, M_ / 128);
    out_gemm_kernel<<<out_grid, 256>>>(Wo, bo, hidden);

    ln_kernel<<<M_, 256>>>(gamma, beta, out);
}

// round 4
// speedup vs baseline: 1.5477x; 1.5477x over previous
#include <cuda_runtime.h>
#include <cuda_bf16.h>
#include <math_constants.h>
#include <cstdint>

#define B_ 8
#define S_ 1024
#define H_ 1024
#define NH_ 16
#define HD_ 64
#define M_ (B_ * S_)        // 8192
#define LN_EPS 1e-12f

// fp32 scratch
__device__ float g_Q[M_ * H_];    // [B*NH][S][HD]
__device__ float g_K[M_ * H_];
__device__ float g_V[M_ * H_];
__device__ float g_ctx[M_ * H_];  // [B,S,H]
__device__ float g_x[M_ * H_];    // residual-added pre-LN

// bf16 hi/lo split scratch (u16 bits)
__device__ unsigned short g_Xhi[M_ * H_];
__device__ unsigned short g_Xlo[M_ * H_];
__device__ unsigned short g_Whi[4 * H_ * H_];   // Wq,Wk,Wv,Wo
__device__ unsigned short g_Wlo[4 * H_ * H_];
__device__ unsigned short g_Chi[M_ * H_];       // ctx split
__device__ unsigned short g_Clo[M_ * H_];

// ---------------------------------------------------------------------------
// helpers (family-agnostic PTX only: ldmatrix sm_75+, mma.sync bf16 sm_80+)
// ---------------------------------------------------------------------------
__device__ __forceinline__ uint32_t smem_u32(const void* p) {
    uint32_t a;
    asm("{ .reg .u64 t; cvta.to.shared.u64 t, %1; cvt.u32.u64 %0, t; }" : "=r"(a) : "l"(p));
    return a;
}
__device__ __forceinline__ void ldm_x4(uint32_t& r0, uint32_t& r1, uint32_t& r2, uint32_t& r3,
                                       uint32_t addr) {
    asm volatile("ldmatrix.sync.aligned.m8n8.x4.shared.b16 {%0,%1,%2,%3}, [%4];"
                 : "=r"(r0), "=r"(r1), "=r"(r2), "=r"(r3) : "r"(addr));
}
__device__ __forceinline__ void mma_bf16(float* d, const uint32_t* a, const uint32_t* b) {
    asm volatile(
        "mma.sync.aligned.m16n8k16.row.col.f32.bf16.bf16.f32 "
        "{%0,%1,%2,%3}, {%4,%5,%6,%7}, {%8,%9}, {%0,%1,%2,%3};"
        : "+f"(d[0]), "+f"(d[1]), "+f"(d[2]), "+f"(d[3])
        : "r"(a[0]), "r"(a[1]), "r"(a[2]), "r"(a[3]), "r"(b[0]), "r"(b[1]));
}

// ---------------------------------------------------------------------------
// split fp32 -> bf16 hi + bf16 lo
// ---------------------------------------------------------------------------
__global__ __launch_bounds__(256) void split_kernel(
    const float* __restrict__ src, unsigned short* __restrict__ hi,
    unsigned short* __restrict__ lo, int n4)
{
    int i = blockIdx.x * 256 + threadIdx.x;
    if (i >= n4) return;
    float4 v = ((const float4*)src)[i];
    float f[4] = {v.x, v.y, v.z, v.w};
    ushort4 hh, ll;
    unsigned short* hp = &hh.x;
    unsigned short* lp = &ll.x;
    #pragma unroll
    for (int j = 0; j < 4; j++) {
        __nv_bfloat16 h = __float2bfloat16(f[j]);
        float r = f[j] - __bfloat162float(h);
        __nv_bfloat16 l = __float2bfloat16(r);
        hp[j] = __bfloat16_as_ushort(h);
        lp[j] = __bfloat16_as_ushort(l);
    }
    ((ushort4*)hi)[i] = hh;
    ((ushort4*)lo)[i] = ll;
}

// ---------------------------------------------------------------------------
// mma.sync split-bf16 GEMM: C[m][n] = sum_k A[m][k]*W[n][k]
// BM=128 BN=128 BK=32, 256 thr (8 warps, 4x2), warp tile 32x64.
// 3 passes: Ahi*Bhi + Ahi*Blo + Alo*Bhi, fp32 accumulate.
// w = wbase+blockIdx.z: 0..2 -> g_Q/K/V (+bias); 3 -> g_x (+bias+residual)
// ---------------------------------------------------------------------------
#define BK 32
#define NCH (H_ / BK)        // 32 chunks
#define STR 40               // smem row stride in halves (padded)
#define MAT_H (128 * STR)    // halves per matrix tile
#define STG_H (4 * MAT_H)    // halves per stage (Ahi,Alo,Bhi,Blo)
#define GEMM_SMEM (2 * STG_H * 2)   // bytes

__global__ __launch_bounds__(256, 1) void gemm_kernel(
    const unsigned short* __restrict__ Ahi, const unsigned short* __restrict__ Alo,
    int wbase,
    const float* __restrict__ bias0, const float* __restrict__ bias1,
    const float* __restrict__ bias2, const float* __restrict__ residual)
{
    extern __shared__ unsigned short sm[];
    const uint32_t sbase = smem_u32(sm);

    const int tid = threadIdx.x;
    const int wid = tid >> 5;
    const int lane = tid & 31;
    const int warp_m = wid & 3;      // 0..3 -> 32 rows
    const int warp_n = wid >> 2;     // 0..1 -> 64 cols
    const int w  = wbase + blockIdx.z;
    const int n0 = blockIdx.x * 128;
    const int m0 = blockIdx.y * 128;

    const unsigned short* Bhi = g_Whi + ((size_t)w << 20);
    const unsigned short* Blo = g_Wlo + ((size_t)w << 20);
    const float* bias = (w == 1) ? bias1 : (w == 2) ? bias2 : bias0;

    float C[2][8][4];
    #pragma unroll
    for (int a = 0; a < 2; a++)
        #pragma unroll
        for (int b = 0; b < 8; b++)
            #pragma unroll
            for (int c = 0; c < 4; c++) C[a][b][c] = 0.f;

    // gmem load indices: idx = tid + t*256, t=0,1 ; row = idx>>2, grp = idx&3 (8 halves)
    const int r0i = tid >> 2, g0 = (tid & 3) * 8;
    const int r1i = r0i + 64;   // (tid+256)>>2

    uint4 pre[8];
    const unsigned short* gsrc[4] = {Ahi, Alo, Bhi, Blo};
    const int gbase[4] = {m0, m0, n0, n0};

    // prefetch chunk 0
    #pragma unroll
    for (int mat = 0; mat < 4; mat++) {
        const unsigned short* sp = gsrc[mat] + (size_t)(gbase[mat]) * H_;
        pre[2 * mat + 0] = *(const uint4*)(sp + (size_t)r0i * H_ + g0);
        pre[2 * mat + 1] = *(const uint4*)(sp + (size_t)r1i * H_ + g0);
    }
    // store chunk 0
    #pragma unroll
    for (int mat = 0; mat < 4; mat++) {
        *(uint4*)(sm + mat * MAT_H + r0i * STR + g0) = pre[2 * mat + 0];
        *(uint4*)(sm + mat * MAT_H + r1i * STR + g0) = pre[2 * mat + 1];
    }
    __syncthreads();

    for (int c = 0; c < NCH; c++) {
        const int buf = c & 1;
        const uint32_t stage = sbase + buf * (STG_H * 2);

        // prefetch next chunk while computing
        if (c + 1 < NCH) {
            const int kc = (c + 1) * BK;
            #pragma unroll
            for (int mat = 0; mat < 4; mat++) {
                const unsigned short* sp = gsrc[mat] + (size_t)(gbase[mat]) * H_ + kc;
                pre[2 * mat + 0] = *(const uint4*)(sp + (size_t)r0i * H_ + g0);
                pre[2 * mat + 1] = *(const uint4*)(sp + (size_t)r1i * H_ + g0);
            }
        }

        // compute on stage buf
        #pragma unroll
        for (int ks = 0; ks < 2; ks++) {
            const int k0 = ks * 16;
            uint32_t ah[2][4], al[2][4];
            #pragma unroll
            for (int mt = 0; mt < 2; mt++) {
                int row = warp_m * 32 + mt * 16 + (lane & 15);
                int col = k0 + (lane >> 4) * 8;
                uint32_t off = (uint32_t)(row * STR + col) * 2;
                ldm_x4(ah[mt][0], ah[mt][1], ah[mt][2], ah[mt][3],
                       stage + 0 * MAT_H * 2 + off);
                ldm_x4(al[mt][0], al[mt][1], al[mt][2], al[mt][3],
                       stage + 1 * MAT_H * 2 + off);
            }
            #pragma unroll
            for (int ntp = 0; ntp < 4; ntp++) {
                int brow = warp_n * 64 + ntp * 16 + (lane & 7) + (lane >> 4) * 8;
                int bcol = k0 + ((lane >> 3) & 1) * 8;
                uint32_t off = (uint32_t)(brow * STR + bcol) * 2;
                uint32_t bh[4], bl[4];
                ldm_x4(bh[0], bh[1], bh[2], bh[3], stage + 2 * MAT_H * 2 + off);
                ldm_x4(bl[0], bl[1], bl[2], bl[3], stage + 3 * MAT_H * 2 + off);
                #pragma unroll
                for (int nt2 = 0; nt2 < 2; nt2++) {
                    const int nt = ntp * 2 + nt2;
                    #pragma unroll
                    for (int mt = 0; mt < 2; mt++) {
                        mma_bf16(C[mt][nt], ah[mt], &bh[nt2 * 2]);
                        mma_bf16(C[mt][nt], ah[mt], &bl[nt2 * 2]);
                        mma_bf16(C[mt][nt], al[mt], &bh[nt2 * 2]);
                    }
                }
            }
        }
        __syncthreads();

        if (c + 1 < NCH) {
            unsigned short* dstg = sm + ((c + 1) & 1) * STG_H;
            #pragma unroll
            for (int mat = 0; mat < 4; mat++) {
                *(uint4*)(dstg + mat * MAT_H + r0i * STR + g0) = pre[2 * mat + 0];
                *(uint4*)(dstg + mat * MAT_H + r1i * STR + g0) = pre[2 * mat + 1];
            }
            __syncthreads();
        }
    }

    // epilogue
    #pragma unroll
    for (int mt = 0; mt < 2; mt++) {
        #pragma unroll
        for (int nt = 0; nt < 8; nt++) {
            const float* d = C[mt][nt];
            int m = m0 + warp_m * 32 + mt * 16 + (lane >> 2);
            int n = n0 + warp_n * 64 + nt * 8 + (lane & 3) * 2;
            float b0 = bias[n], b1 = bias[n + 1];
            if (w < 3) {
                float* outp = (w == 0 ? g_Q : (w == 1 ? g_K : g_V));
                int h = n >> 6, dd = n & 63;
                #pragma unroll
                for (int rr = 0; rr < 2; rr++) {
                    int mm = m + rr * 8;
                    int bb = mm >> 10, ss = mm & 1023;
                    float* dst = outp + ((size_t)(bb * NH_ + h) * S_ + ss) * HD_ + dd;
                    float2 o = make_float2(d[rr * 2 + 0] + b0, d[rr * 2 + 1] + b1);
                    *(float2*)dst = o;
                }
            } else {
                #pragma unroll
                for (int rr = 0; rr < 2; rr++) {
                    int mm = m + rr * 8;
                    size_t idx = (size_t)mm * H_ + n;
                    float2 res = *(const float2*)&residual[idx];
                    float2 o = make_float2(d[rr * 2 + 0] + b0 + res.x,
                                           d[rr * 2 + 1] + b1 + res.y);
                    *(float2*)&g_x[idx] = o;
                }
            }
        }
    }
}

// ---------------------------------------------------------------------------
// Flash attention: 1 thread = 1 query row. grid (S/128=8, B*NH=128), 128 thr.
// ---------------------------------------------------------------------------
__global__ __launch_bounds__(128) void attn_kernel(const float* __restrict__ mask)
{
    const int bh  = blockIdx.y;
    const int qt  = blockIdx.x;
    const int tid = threadIdx.x;
    const int b   = bh >> 4;
    const int h   = bh & 15;

    const float* Qp = g_Q + (size_t)bh * S_ * HD_;
    const float* Kp = g_K + (size_t)bh * S_ * HD_;
    const float* Vp = g_V + (size_t)bh * S_ * HD_;

    const int sq = qt * 128 + tid;

    float4 q[16];
    #pragma unroll
    for (int i = 0; i < 16; i++) q[i] = *(const float4*)&Qp[(size_t)sq * HD_ + i * 4];

    float4 acc[16];
    #pragma unroll
    for (int i = 0; i < 16; i++) acc[i] = make_float4(0.f, 0.f, 0.f, 0.f);

    float mx = -CUDART_INF_F;
    float l  = 0.f;

    __shared__ float Ks[32][64];
    __shared__ float Vs[32][64];

    for (int kt = 0; kt < S_ / 32; kt++) {
        #pragma unroll
        for (int it = 0; it < 4; it++) {
            int f = it * 128 + tid;
            int j = f >> 4;
            int cc = (f & 15) * 4;
            *(float4*)&Ks[j][cc] = *(const float4*)&Kp[(size_t)(kt * 32 + j) * HD_ + cc];
            *(float4*)&Vs[j][cc] = *(const float4*)&Vp[(size_t)(kt * 32 + j) * HD_ + cc];
        }
        __syncthreads();

        float s[32];
        #pragma unroll
        for (int j = 0; j < 32; j++) {
            const float4* kr = (const float4*)Ks[j];
            float sv = 0.f;
            #pragma unroll
            for (int i = 0; i < 16; i++) {
                float4 kk = kr[i];
                sv = fmaf(q[i].x, kk.x, sv);
                sv = fmaf(q[i].y, kk.y, sv);
                sv = fmaf(q[i].z, kk.z, sv);
                sv = fmaf(q[i].w, kk.w, sv);
            }
            s[j] = sv * 0.125f + mask[b * S_ + kt * 32 + j];
        }

        float tmax = mx;
        #pragma unroll
        for (int j = 0; j < 32; j++) tmax = fmaxf(tmax, s[j]);

        float scale = __expf(mx - tmax);
        mx = tmax;
        l *= scale;
        #pragma unroll
        for (int i = 0; i < 16; i++) {
            acc[i].x *= scale; acc[i].y *= scale;
            acc[i].z *= scale; acc[i].w *= scale;
        }

        #pragma unroll
        for (int j = 0; j < 32; j++) {
            float p = __expf(s[j] - mx);
            l += p;
            const float4* vr = (const float4*)Vs[j];
            #pragma unroll
            for (int i = 0; i < 16; i++) {
                float4 vv = vr[i];
                acc[i].x = fmaf(p, vv.x, acc[i].x);
                acc[i].y = fmaf(p, vv.y, acc[i].y);
                acc[i].z = fmaf(p, vv.z, acc[i].z);
                acc[i].w = fmaf(p, vv.w, acc[i].w);
            }
        }
        __syncthreads();
    }

    float inv = 1.f / l;
    float* op = g_ctx + ((size_t)(b * S_ + sq)) * H_ + h * HD_;
    #pragma unroll
    for (int i = 0; i < 16; i++) {
        float4 o;
        o.x = acc[i].x * inv; o.y = acc[i].y * inv;
        o.z = acc[i].z * inv; o.w = acc[i].w * inv;
        *(float4*)&op[i * 4] = o;
    }
}

// ---------------------------------------------------------------------------
// LayerNorm
// ---------------------------------------------------------------------------
__global__ __launch_bounds__(256) void ln_kernel(
    const float* __restrict__ gamma, const float* __restrict__ beta,
    float* __restrict__ out)
{
    const int row = blockIdx.x;
    const int tid = threadIdx.x;
    const float* x = g_x + (size_t)row * H_;

    float4 v = *(const float4*)&x[tid * 4];
    float s  = v.x + v.y + v.z + v.w;
    float ss = v.x * v.x + v.y * v.y + v.z * v.z + v.w * v.w;

    #pragma unroll
    for (int o = 16; o > 0; o >>= 1) {
        s  += __shfl_xor_sync(0xffffffffu, s,  o);
        ss += __shfl_xor_sync(0xffffffffu, ss, o);
    }
    __shared__ float rs[8], rss[8];
    int wid = tid >> 5, lid = tid & 31;
    if (lid == 0) { rs[wid] = s; rss[wid] = ss; }
    __syncthreads();
    if (wid == 0) {
        float a = (lid < 8) ? rs[lid]  : 0.f;
        float c = (lid < 8) ? rss[lid] : 0.f;
        #pragma unroll
        for (int o = 4; o > 0; o >>= 1) {
            a += __shfl_xor_sync(0xffffffffu, a, o);
            c += __shfl_xor_sync(0xffffffffu, c, o);
        }
        if (lid == 0) { rs[0] = a; rss[0] = c; }
    }
    __syncthreads();

    float mean = rs[0] * (1.f / H_);
    float var  = rss[0] * (1.f / H_) - mean * mean;
    float rstd = rsqrtf(var + LN_EPS);

    float4 g = *(const float4*)&gamma[tid * 4];
    float4 bt = *(const float4*)&beta[tid * 4];
    float4 y;
    y.x = (v.x - mean) * rstd * g.x + bt.x;
    y.y = (v.y - mean) * rstd * g.y + bt.y;
    y.z = (v.z - mean) * rstd * g.z + bt.z;
    y.w = (v.w - mean) * rstd * g.w + bt.w;
    *(float4*)&out[(size_t)row * H_ + tid * 4] = y;
}

// ---------------------------------------------------------------------------
extern "C" void kernel_launch(void* const* d_in, const int* in_sizes, int n_in,
                              void* d_out, int out_size)
{
    const float* hidden = (const float*)d_in[0];
    const float* mask   = (const float*)d_in[1];
    const float* Wq     = (const float*)d_in[2];
    const float* bq     = (const float*)d_in[3];
    const float* Wk     = (const float*)d_in[4];
    const float* bk     = (const float*)d_in[5];
    const float* Wv     = (const float*)d_in[6];
    const float* bv     = (const float*)d_in[7];
    const float* Wo     = (const float*)d_in[8];
    const float* bo     = (const float*)d_in[9];
    const float* gamma  = (const float*)d_in[10];
    const float* beta   = (const float*)d_in[11];
    float* out          = (float*)d_out;

    static int attr_set = 0;
    if (!attr_set) {
        cudaFuncSetAttribute(gemm_kernel, cudaFuncAttributeMaxDynamicSharedMemorySize, GEMM_SMEM);
        attr_set = 1;
    }

    unsigned short *xhi, *xlo, *whi, *wlo, *chi, *clo;
    cudaGetSymbolAddress((void**)&xhi, g_Xhi);
    cudaGetSymbolAddress((void**)&xlo, g_Xlo);
    cudaGetSymbolAddress((void**)&whi, g_Whi);
    cudaGetSymbolAddress((void**)&wlo, g_Wlo);
    cudaGetSymbolAddress((void**)&chi, g_Chi);
    cudaGetSymbolAddress((void**)&clo, g_Clo);
    float* ctxp;
    cudaGetSymbolAddress((void**)&ctxp, g_ctx);

    const int NW = H_ * H_ / 4;
    split_kernel<<<(M_ * H_ / 4 + 255) / 256, 256>>>(hidden, xhi, xlo, M_ * H_ / 4);
    split_kernel<<<(NW + 255) / 256, 256>>>(Wq, whi + 0 * H_ * H_, wlo + 0 * H_ * H_, NW);
    split_kernel<<<(NW + 255) / 256, 256>>>(Wk, whi + 1 * H_ * H_, wlo + 1 * H_ * H_, NW);
    split_kernel<<<(NW + 255) / 256, 256>>>(Wv, whi + 2 * H_ * H_, wlo + 2 * H_ * H_, NW);
    split_kernel<<<(NW + 255) / 256, 256>>>(Wo, whi + 3 * H_ * H_, wlo + 3 * H_ * H_, NW);

    dim3 qkv_grid(H_ / 128, M_ / 128, 3);
    gemm_kernel<<<qkv_grid, 256, GEMM_SMEM>>>(xhi, xlo, 0, bq, bk, bv, nullptr);

    dim3 attn_grid(S_ / 128, B_ * NH_);
    attn_kernel<<<attn_grid, 128>>>(mask);

    split_kernel<<<(M_ * H_ / 4 + 255) / 256, 256>>>(ctxp, chi, clo, M_ * H_ / 4);

    dim3 out_grid(H_ / 128, M_ / 128, 1);
    gemm_kernel<<<out_grid, 256, GEMM_SMEM>>>(chi, clo, 3, bo, nullptr, nullptr, hidden);

    ln_kernel<<<M_, 256>>>(gamma, beta, out);
}

// round 5
// speedup vs baseline: 2.8429x; 1.8368x over previous
#include <cuda_runtime.h>
#include <cuda_bf16.h>
#include <math_constants.h>
#include <cstdint>

#define B_ 8
#define S_ 1024
#define H_ 1024
#define NH_ 16
#define HD_ 64
#define M_ (B_ * S_)        // 8192
#define LN_EPS 1e-12f

// fp32 scratch
__device__ float g_x[M_ * H_];    // residual-added pre-LN

// bf16 hi/lo split scratch (u16 bits)
__device__ unsigned short g_Xhi[M_ * H_];
__device__ unsigned short g_Xlo[M_ * H_];
__device__ unsigned short g_Whi[4 * H_ * H_];   // Wq,Wk,Wv,Wo
__device__ unsigned short g_Wlo[4 * H_ * H_];
__device__ unsigned short g_Qh[M_ * H_];        // [B*NH][S][HD]
__device__ unsigned short g_Ql[M_ * H_];
__device__ unsigned short g_Kh[M_ * H_];
__device__ unsigned short g_Kl[M_ * H_];
__device__ unsigned short g_Vh[M_ * H_];
__device__ unsigned short g_Vl[M_ * H_];
__device__ unsigned short g_Chi[M_ * H_];       // ctx split [B,S,H]
__device__ unsigned short g_Clo[M_ * H_];

// ---------------------------------------------------------------------------
// helpers (family-agnostic PTX: ldmatrix sm_75+, mma.sync bf16 sm_80+)
// ---------------------------------------------------------------------------
__device__ __forceinline__ uint32_t smem_u32(const void* p) {
    uint32_t a;
    asm("{ .reg .u64 t; cvta.to.shared.u64 t, %1; cvt.u32.u64 %0, t; }" : "=r"(a) : "l"(p));
    return a;
}
__device__ __forceinline__ void ldm_x4(uint32_t& r0, uint32_t& r1, uint32_t& r2, uint32_t& r3,
                                       uint32_t addr) {
    asm volatile("ldmatrix.sync.aligned.m8n8.x4.shared.b16 {%0,%1,%2,%3}, [%4];"
                 : "=r"(r0), "=r"(r1), "=r"(r2), "=r"(r3) : "r"(addr));
}
__device__ __forceinline__ void ldm_x4_t(uint32_t& r0, uint32_t& r1, uint32_t& r2, uint32_t& r3,
                                         uint32_t addr) {
    asm volatile("ldmatrix.sync.aligned.m8n8.x4.trans.shared.b16 {%0,%1,%2,%3}, [%4];"
                 : "=r"(r0), "=r"(r1), "=r"(r2), "=r"(r3) : "r"(addr));
}
__device__ __forceinline__ void mma_bf16(float* d, const uint32_t* a, const uint32_t* b) {
    asm volatile(
        "mma.sync.aligned.m16n8k16.row.col.f32.bf16.bf16.f32 "
        "{%0,%1,%2,%3}, {%4,%5,%6,%7}, {%8,%9}, {%0,%1,%2,%3};"
        : "+f"(d[0]), "+f"(d[1]), "+f"(d[2]), "+f"(d[3])
        : "r"(a[0]), "r"(a[1]), "r"(a[2]), "r"(a[3]), "r"(b[0]), "r"(b[1]));
}
// split two fp32 into packed bf16x2 hi + bf16x2 lo
__device__ __forceinline__ void pack_split(float a, float b, uint32_t& hi, uint32_t& lo) {
    __nv_bfloat16 ha = __float2bfloat16(a), hb = __float2bfloat16(b);
    __nv_bfloat16 la = __float2bfloat16(a - __bfloat162float(ha));
    __nv_bfloat16 lb = __float2bfloat16(b - __bfloat162float(hb));
    hi = (uint32_t)__bfloat16_as_ushort(ha) | ((uint32_t)__bfloat16_as_ushort(hb) << 16);
    lo = (uint32_t)__bfloat16_as_ushort(la) | ((uint32_t)__bfloat16_as_ushort(lb) << 16);
}

// ---------------------------------------------------------------------------
// split fp32 -> bf16 hi + bf16 lo (inputs X and weights)
// ---------------------------------------------------------------------------
__global__ __launch_bounds__(256) void split_kernel(
    const float* __restrict__ src, unsigned short* __restrict__ hi,
    unsigned short* __restrict__ lo, int n4)
{
    int i = blockIdx.x * 256 + threadIdx.x;
    if (i >= n4) return;
    float4 v = ((const float4*)src)[i];
    float f[4] = {v.x, v.y, v.z, v.w};
    ushort4 hh, ll;
    unsigned short* hp = &hh.x;
    unsigned short* lp = &ll.x;
    #pragma unroll
    for (int j = 0; j < 4; j++) {
        __nv_bfloat16 h = __float2bfloat16(f[j]);
        float r = f[j] - __bfloat162float(h);
        __nv_bfloat16 l = __float2bfloat16(r);
        hp[j] = __bfloat16_as_ushort(h);
        lp[j] = __bfloat16_as_ushort(l);
    }
    ((ushort4*)hi)[i] = hh;
    ((ushort4*)lo)[i] = ll;
}

// ---------------------------------------------------------------------------
// mma.sync split-bf16 GEMM: C[m][n] = sum_k A[m][k]*W[n][k]
// BM=128 BN=128 BK=32, 256 thr (8 warps 4x2), warp tile 32x64, 3 passes.
// w<3: emit split bf16 into g_{Q,K,V}{h,l} (+bias). w==3: g_x (+bias+residual).
// ---------------------------------------------------------------------------
#define BK 32
#define NCH (H_ / BK)
#define STR 40
#define MAT_H (128 * STR)
#define STG_H (4 * MAT_H)
#define GEMM_SMEM (2 * STG_H * 2)

__global__ __launch_bounds__(256, 1) void gemm_kernel(
    const unsigned short* __restrict__ Ahi, const unsigned short* __restrict__ Alo,
    int wbase,
    const float* __restrict__ bias0, const float* __restrict__ bias1,
    const float* __restrict__ bias2, const float* __restrict__ residual)
{
    extern __shared__ unsigned short sm[];
    const uint32_t sbase = smem_u32(sm);

    const int tid = threadIdx.x;
    const int wid = tid >> 5;
    const int lane = tid & 31;
    const int warp_m = wid & 3;
    const int warp_n = wid >> 2;
    const int w  = wbase + blockIdx.z;
    const int n0 = blockIdx.x * 128;
    const int m0 = blockIdx.y * 128;

    const unsigned short* Bhi = g_Whi + ((size_t)w << 20);
    const unsigned short* Blo = g_Wlo + ((size_t)w << 20);
    const float* bias = (w == 1) ? bias1 : (w == 2) ? bias2 : bias0;

    float C[2][8][4];
    #pragma unroll
    for (int a = 0; a < 2; a++)
        #pragma unroll
        for (int b = 0; b < 8; b++)
            #pragma unroll
            for (int c = 0; c < 4; c++) C[a][b][c] = 0.f;

    const int r0i = tid >> 2, g0 = (tid & 3) * 8;
    const int r1i = r0i + 64;

    uint4 pre[8];
    const unsigned short* gsrc[4] = {Ahi, Alo, Bhi, Blo};
    const int gbase[4] = {m0, m0, n0, n0};

    #pragma unroll
    for (int mat = 0; mat < 4; mat++) {
        const unsigned short* sp = gsrc[mat] + (size_t)(gbase[mat]) * H_;
        pre[2 * mat + 0] = *(const uint4*)(sp + (size_t)r0i * H_ + g0);
        pre[2 * mat + 1] = *(const uint4*)(sp + (size_t)r1i * H_ + g0);
    }
    #pragma unroll
    for (int mat = 0; mat < 4; mat++) {
        *(uint4*)(sm + mat * MAT_H + r0i * STR + g0) = pre[2 * mat + 0];
        *(uint4*)(sm + mat * MAT_H + r1i * STR + g0) = pre[2 * mat + 1];
    }
    __syncthreads();

    for (int c = 0; c < NCH; c++) {
        const int buf = c & 1;
        const uint32_t stage = sbase + buf * (STG_H * 2);

        if (c + 1 < NCH) {
            const int kc = (c + 1) * BK;
            #pragma unroll
            for (int mat = 0; mat < 4; mat++) {
                const unsigned short* sp = gsrc[mat] + (size_t)(gbase[mat]) * H_ + kc;
                pre[2 * mat + 0] = *(const uint4*)(sp + (size_t)r0i * H_ + g0);
                pre[2 * mat + 1] = *(const uint4*)(sp + (size_t)r1i * H_ + g0);
            }
        }

        #pragma unroll
        for (int ks = 0; ks < 2; ks++) {
            const int k0 = ks * 16;
            uint32_t ah[2][4], al[2][4];
            #pragma unroll
            for (int mt = 0; mt < 2; mt++) {
                int row = warp_m * 32 + mt * 16 + (lane & 15);
                int col = k0 + (lane >> 4) * 8;
                uint32_t off = (uint32_t)(row * STR + col) * 2;
                ldm_x4(ah[mt][0], ah[mt][1], ah[mt][2], ah[mt][3],
                       stage + 0 * MAT_H * 2 + off);
                ldm_x4(al[mt][0], al[mt][1], al[mt][2], al[mt][3],
                       stage + 1 * MAT_H * 2 + off);
            }
            #pragma unroll
            for (int ntp = 0; ntp < 4; ntp++) {
                int brow = warp_n * 64 + ntp * 16 + (lane & 7) + (lane >> 4) * 8;
                int bcol = k0 + ((lane >> 3) & 1) * 8;
                uint32_t off = (uint32_t)(brow * STR + bcol) * 2;
                uint32_t bh[4], bl[4];
                ldm_x4(bh[0], bh[1], bh[2], bh[3], stage + 2 * MAT_H * 2 + off);
                ldm_x4(bl[0], bl[1], bl[2], bl[3], stage + 3 * MAT_H * 2 + off);
                #pragma unroll
                for (int nt2 = 0; nt2 < 2; nt2++) {
                    const int nt = ntp * 2 + nt2;
                    #pragma unroll
                    for (int mt = 0; mt < 2; mt++) {
                        mma_bf16(C[mt][nt], ah[mt], &bh[nt2 * 2]);
                        mma_bf16(C[mt][nt], ah[mt], &bl[nt2 * 2]);
                        mma_bf16(C[mt][nt], al[mt], &bh[nt2 * 2]);
                    }
                }
            }
        }
        __syncthreads();

        if (c + 1 < NCH) {
            unsigned short* dstg = sm + ((c + 1) & 1) * STG_H;
            #pragma unroll
            for (int mat = 0; mat < 4; mat++) {
                *(uint4*)(dstg + mat * MAT_H + r0i * STR + g0) = pre[2 * mat + 0];
                *(uint4*)(dstg + mat * MAT_H + r1i * STR + g0) = pre[2 * mat + 1];
            }
            __syncthreads();
        }
    }

    // epilogue
    unsigned short* oh = (w == 0) ? g_Qh : (w == 1) ? g_Kh : g_Vh;
    unsigned short* ol = (w == 0) ? g_Ql : (w == 1) ? g_Kl : g_Vl;
    #pragma unroll
    for (int mt = 0; mt < 2; mt++) {
        #pragma unroll
        for (int nt = 0; nt < 8; nt++) {
            const float* d = C[mt][nt];
            int m = m0 + warp_m * 32 + mt * 16 + (lane >> 2);
            int n = n0 + warp_n * 64 + nt * 8 + (lane & 3) * 2;
            float b0 = bias[n], b1 = bias[n + 1];
            if (w < 3) {
                int h = n >> 6, dd = n & 63;
                #pragma unroll
                for (int rr = 0; rr < 2; rr++) {
                    int mm = m + rr * 8;
                    int bb = mm >> 10, ss = mm & 1023;
                    size_t o = ((size_t)(bb * NH_ + h) * S_ + ss) * HD_ + dd;
                    uint32_t hi, lo;
                    pack_split(d[rr * 2 + 0] + b0, d[rr * 2 + 1] + b1, hi, lo);
                    *(uint32_t*)&oh[o] = hi;
                    *(uint32_t*)&ol[o] = lo;
                }
            } else {
                #pragma unroll
                for (int rr = 0; rr < 2; rr++) {
                    int mm = m + rr * 8;
                    size_t idx = (size_t)mm * H_ + n;
                    float2 res = *(const float2*)&residual[idx];
                    float2 o = make_float2(d[rr * 2 + 0] + b0 + res.x,
                                           d[rr * 2 + 1] + b1 + res.y);
                    *(float2*)&g_x[idx] = o;
                }
            }
        }
    }
}

// ---------------------------------------------------------------------------
// Tensor-core flash attention, split-bf16, fp32 softmax.
// grid (S/64=16, B*NH=128), 128 thr (4 warps, 16 q-rows each).
// ---------------------------------------------------------------------------
#define ASTR 72   // smem row stride (u16), 64 cols + 8 pad

__global__ __launch_bounds__(128) void attn_kernel(const float* __restrict__ mask)
{
    __shared__ unsigned short Kh[64 * ASTR], Kl[64 * ASTR];
    __shared__ unsigned short Vh[64 * ASTR], Vl[64 * ASTR];
    __shared__ float msk[S_];

    const int bh  = blockIdx.y;
    const int qt  = blockIdx.x;
    const int tid = threadIdx.x;
    const int wid = tid >> 5;
    const int lane = tid & 31;
    const int b   = bh >> 4;
    const int h   = bh & 15;
    const size_t base = (size_t)bh * S_ * HD_;

    const uint32_t sKh = smem_u32(Kh), sKl = smem_u32(Kl);
    const uint32_t sVh = smem_u32(Vh), sVl = smem_u32(Vl);

    // mask row -> smem
    #pragma unroll
    for (int t = 0; t < 2; t++)
        ((float4*)msk)[tid + t * 128] = ((const float4*)(mask + (size_t)b * S_))[tid + t * 128];

    // stage Q tile into Kh/Kl, then ldmatrix into regs
    #pragma unroll
    for (int t = 0; t < 4; t++) {
        int idx = tid + t * 128;
        int row = idx >> 3, g = (idx & 7) * 8;
        size_t go = base + (size_t)(qt * 64 + row) * HD_ + g;
        *(uint4*)&Kh[row * ASTR + g] = *(const uint4*)&g_Qh[go];
        *(uint4*)&Kl[row * ASTR + g] = *(const uint4*)&g_Ql[go];
    }
    __syncthreads();

    uint32_t qh[4][4], ql[4][4];
    #pragma unroll
    for (int ks = 0; ks < 4; ks++) {
        int row = wid * 16 + (lane & 15);
        int col = ks * 16 + (lane >> 4) * 8;
        uint32_t off = (uint32_t)(row * ASTR + col) * 2;
        ldm_x4(qh[ks][0], qh[ks][1], qh[ks][2], qh[ks][3], sKh + off);
        ldm_x4(ql[ks][0], ql[ks][1], ql[ks][2], ql[ks][3], sKl + off);
    }
    __syncthreads();

    float Co[8][4];
    #pragma unroll
    for (int i = 0; i < 8; i++)
        #pragma unroll
        for (int j = 0; j < 4; j++) Co[i][j] = 0.f;
    float m0 = -CUDART_INF_F, m1 = -CUDART_INF_F, l0 = 0.f, l1 = 0.f;

    for (int kt = 0; kt < S_ / 64; kt++) {
        // load K/V hi+lo tiles
        #pragma unroll
        for (int t = 0; t < 4; t++) {
            int idx = tid + t * 128;
            int row = idx >> 3, g = (idx & 7) * 8;
            size_t go = base + (size_t)(kt * 64 + row) * HD_ + g;
            *(uint4*)&Kh[row * ASTR + g] = *(const uint4*)&g_Kh[go];
            *(uint4*)&Kl[row * ASTR + g] = *(const uint4*)&g_Kl[go];
            *(uint4*)&Vh[row * ASTR + g] = *(const uint4*)&g_Vh[go];
            *(uint4*)&Vl[row * ASTR + g] = *(const uint4*)&g_Vl[go];
        }
        __syncthreads();

        // S = Q K^T (3 split passes)
        float Cs[8][4];
        #pragma unroll
        for (int i = 0; i < 8; i++)
            #pragma unroll
            for (int j = 0; j < 4; j++) Cs[i][j] = 0.f;

        #pragma unroll
        for (int ks = 0; ks < 4; ks++) {
            #pragma unroll
            for (int ntp = 0; ntp < 4; ntp++) {
                int brow = ntp * 16 + (lane & 7) + (lane >> 4) * 8;
                int bcol = ks * 16 + ((lane >> 3) & 1) * 8;
                uint32_t off = (uint32_t)(brow * ASTR + bcol) * 2;
                uint32_t kbh[4], kbl[4];
                ldm_x4(kbh[0], kbh[1], kbh[2], kbh[3], sKh + off);
                ldm_x4(kbl[0], kbl[1], kbl[2], kbl[3], sKl + off);
                #pragma unroll
                for (int nt2 = 0; nt2 < 2; nt2++) {
                    const int nt = ntp * 2 + nt2;
                    mma_bf16(Cs[nt], qh[ks], &kbh[nt2 * 2]);
                    mma_bf16(Cs[nt], qh[ks], &kbl[nt2 * 2]);
                    mma_bf16(Cs[nt], ql[ks], &kbh[nt2 * 2]);
                }
            }
        }

        // scale + mask + online softmax
        float mn0 = m0, mn1 = m1;
        #pragma unroll
        for (int nt = 0; nt < 8; nt++) {
            int col = kt * 64 + nt * 8 + (lane & 3) * 2;
            float mka = msk[col], mkb = msk[col + 1];
            Cs[nt][0] = fmaf(Cs[nt][0], 0.125f, mka);
            Cs[nt][1] = fmaf(Cs[nt][1], 0.125f, mkb);
            Cs[nt][2] = fmaf(Cs[nt][2], 0.125f, mka);
            Cs[nt][3] = fmaf(Cs[nt][3], 0.125f, mkb);
            mn0 = fmaxf(mn0, fmaxf(Cs[nt][0], Cs[nt][1]));
            mn1 = fmaxf(mn1, fmaxf(Cs[nt][2], Cs[nt][3]));
        }
        mn0 = fmaxf(mn0, __shfl_xor_sync(0xffffffffu, mn0, 1));
        mn0 = fmaxf(mn0, __shfl_xor_sync(0xffffffffu, mn0, 2));
        mn1 = fmaxf(mn1, __shfl_xor_sync(0xffffffffu, mn1, 1));
        mn1 = fmaxf(mn1, __shfl_xor_sync(0xffffffffu, mn1, 2));

        float f0 = __expf(m0 - mn0), f1 = __expf(m1 - mn1);
        m0 = mn0; m1 = mn1;
        l0 *= f0; l1 *= f1;
        #pragma unroll
        for (int nt = 0; nt < 8; nt++) {
            Co[nt][0] *= f0; Co[nt][1] *= f0;
            Co[nt][2] *= f1; Co[nt][3] *= f1;
        }
        #pragma unroll
        for (int nt = 0; nt < 8; nt++) {
            Cs[nt][0] = __expf(Cs[nt][0] - m0);
            Cs[nt][1] = __expf(Cs[nt][1] - m0);
            Cs[nt][2] = __expf(Cs[nt][2] - m1);
            Cs[nt][3] = __expf(Cs[nt][3] - m1);
            l0 += Cs[nt][0] + Cs[nt][1];
            l1 += Cs[nt][2] + Cs[nt][3];
        }

        // O += P V (3 split passes)
        #pragma unroll
        for (int kc = 0; kc < 4; kc++) {
            uint32_t phi[4], plo[4];
            pack_split(Cs[2 * kc][0],     Cs[2 * kc][1],     phi[0], plo[0]);
            pack_split(Cs[2 * kc][2],     Cs[2 * kc][3],     phi[1], plo[1]);
            pack_split(Cs[2 * kc + 1][0], Cs[2 * kc + 1][1], phi[2], plo[2]);
            pack_split(Cs[2 * kc + 1][2], Cs[2 * kc + 1][3], phi[3], plo[3]);
            #pragma unroll
            for (int ntp = 0; ntp < 4; ntp++) {
                uint32_t off = (uint32_t)((kc * 16 + (lane & 15)) * ASTR +
                                          ntp * 16 + (lane >> 4) * 8) * 2;
                uint32_t vbh[4], vbl[4];
                ldm_x4_t(vbh[0], vbh[1], vbh[2], vbh[3], sVh + off);
                ldm_x4_t(vbl[0], vbl[1], vbl[2], vbl[3], sVl + off);
                #pragma unroll
                for (int nt2 = 0; nt2 < 2; nt2++) {
                    const int nt = ntp * 2 + nt2;
                    mma_bf16(Co[nt], phi, &vbh[nt2 * 2]);
                    mma_bf16(Co[nt], plo, &vbh[nt2 * 2]);
                    mma_bf16(Co[nt], phi, &vbl[nt2 * 2]);
                }
            }
        }
        __syncthreads();
    }

    l0 += __shfl_xor_sync(0xffffffffu, l0, 1);
    l0 += __shfl_xor_sync(0xffffffffu, l0, 2);
    l1 += __shfl_xor_sync(0xffffffffu, l1, 1);
    l1 += __shfl_xor_sync(0xffffffffu, l1, 2);
    float inv0 = 1.f / l0, inv1 = 1.f / l1;

    const int s0 = qt * 64 + wid * 16 + (lane >> 2);
    #pragma unroll
    for (int nt = 0; nt < 8; nt++) {
        int col = h * HD_ + nt * 8 + (lane & 3) * 2;
        size_t o0 = (size_t)(b * S_ + s0) * H_ + col;
        size_t o1 = (size_t)(b * S_ + s0 + 8) * H_ + col;
        uint32_t hi, lo;
        pack_split(Co[nt][0] * inv0, Co[nt][1] * inv0, hi, lo);
        *(uint32_t*)&g_Chi[o0] = hi;
        *(uint32_t*)&g_Clo[o0] = lo;
        pack_split(Co[nt][2] * inv1, Co[nt][3] * inv1, hi, lo);
        *(uint32_t*)&g_Chi[o1] = hi;
        *(uint32_t*)&g_Clo[o1] = lo;
    }
}

// ---------------------------------------------------------------------------
// LayerNorm
// ---------------------------------------------------------------------------
__global__ __launch_bounds__(256) void ln_kernel(
    const float* __restrict__ gamma, const float* __restrict__ beta,
    float* __restrict__ out)
{
    const int row = blockIdx.x;
    const int tid = threadIdx.x;
    const float* x = g_x + (size_t)row * H_;

    float4 v = *(const float4*)&x[tid * 4];
    float s  = v.x + v.y + v.z + v.w;
    float ss = v.x * v.x + v.y * v.y + v.z * v.z + v.w * v.w;

    #pragma unroll
    for (int o = 16; o > 0; o >>= 1) {
        s  += __shfl_xor_sync(0xffffffffu, s,  o);
        ss += __shfl_xor_sync(0xffffffffu, ss, o);
    }
    __shared__ float rs[8], rss[8];
    int wid = tid >> 5, lid = tid & 31;
    if (lid == 0) { rs[wid] = s; rss[wid] = ss; }
    __syncthreads();
    if (wid == 0) {
        float a = (lid < 8) ? rs[lid]  : 0.f;
        float c = (lid < 8) ? rss[lid] : 0.f;
        #pragma unroll
        for (int o = 4; o > 0; o >>= 1) {
            a += __shfl_xor_sync(0xffffffffu, a, o);
            c += __shfl_xor_sync(0xffffffffu, c, o);
        }
        if (lid == 0) { rs[0] = a; rss[0] = c; }
    }
    __syncthreads();

    float mean = rs[0] * (1.f / H_);
    float var  = rss[0] * (1.f / H_) - mean * mean;
    float rstd = rsqrtf(var + LN_EPS);

    float4 g = *(const float4*)&gamma[tid * 4];
    float4 bt = *(const float4*)&beta[tid * 4];
    float4 y;
    y.x = (v.x - mean) * rstd * g.x + bt.x;
    y.y = (v.y - mean) * rstd * g.y + bt.y;
    y.z = (v.z - mean) * rstd * g.z + bt.z;
    y.w = (v.w - mean) * rstd * g.w + bt.w;
    *(float4*)&out[(size_t)row * H_ + tid * 4] = y;
}

// ---------------------------------------------------------------------------
extern "C" void kernel_launch(void* const* d_in, const int* in_sizes, int n_in,
                              void* d_out, int out_size)
{
    const float* hidden = (const float*)d_in[0];
    const float* mask   = (const float*)d_in[1];
    const float* Wq     = (const float*)d_in[2];
    const float* bq     = (const float*)d_in[3];
    const float* Wk     = (const float*)d_in[4];
    const float* bk     = (const float*)d_in[5];
    const float* Wv     = (const float*)d_in[6];
    const float* bv     = (const float*)d_in[7];
    const float* Wo     = (const float*)d_in[8];
    const float* bo     = (const float*)d_in[9];
    const float* gamma  = (const float*)d_in[10];
    const float* beta   = (const float*)d_in[11];
    float* out          = (float*)d_out;

    static int attr_set = 0;
    if (!attr_set) {
        cudaFuncSetAttribute(gemm_kernel, cudaFuncAttributeMaxDynamicSharedMemorySize, GEMM_SMEM);
        attr_set = 1;
    }

    unsigned short *xhi, *xlo, *whi, *wlo, *chi, *clo;
    cudaGetSymbolAddress((void**)&xhi, g_Xhi);
    cudaGetSymbolAddress((void**)&xlo, g_Xlo);
    cudaGetSymbolAddress((void**)&whi, g_Whi);
    cudaGetSymbolAddress((void**)&wlo, g_Wlo);
    cudaGetSymbolAddress((void**)&chi, g_Chi);
    cudaGetSymbolAddress((void**)&clo, g_Clo);

    const int NW = H_ * H_ / 4;
    split_kernel<<<(M_ * H_ / 4 + 255) / 256, 256>>>(hidden, xhi, xlo, M_ * H_ / 4);
    split_kernel<<<(NW + 255) / 256, 256>>>(Wq, whi + 0 * H_ * H_, wlo + 0 * H_ * H_, NW);
    split_kernel<<<(NW + 255) / 256, 256>>>(Wk, whi + 1 * H_ * H_, wlo + 1 * H_ * H_, NW);
    split_kernel<<<(NW + 255) / 256, 256>>>(Wv, whi + 2 * H_ * H_, wlo + 2 * H_ * H_, NW);
    split_kernel<<<(NW + 255) / 256, 256>>>(Wo, whi + 3 * H_ * H_, wlo + 3 * H_ * H_, NW);

    dim3 qkv_grid(H_ / 128, M_ / 128, 3);
    gemm_kernel<<<qkv_grid, 256, GEMM_SMEM>>>(xhi, xlo, 0, bq, bk, bv, nullptr);

    dim3 attn_grid(S_ / 64, B_ * NH_);
    attn_kernel<<<attn_grid, 128>>>(mask);

    dim3 out_grid(H_ / 128, M_ / 128, 1);
    gemm_kernel<<<out_grid, 256, GEMM_SMEM>>>(chi, clo, 3, bo, nullptr, nullptr, hidden);

    ln_kernel<<<M_, 256>>>(gamma, beta, out);
}